// round 7
// baseline (speedup 1.0000x reference)
#include <cuda_runtime.h>
#include <cstdint>

#define N_NODES 50000
#define EMB 128
#define NRBF 20

// Scratch (static device arrays are allowed; runtime alloc is not)
__device__ float g_h[(size_t)N_NODES * EMB];         // silu(s@W1+b1)
__device__ float g_spass[(size_t)N_NODES * 3 * EMB]; // h@W2+b2

// ---------- f32x2 helpers ----------
__device__ __forceinline__ unsigned long long fma2(unsigned long long a,
                                                   unsigned long long b,
                                                   unsigned long long c) {
    unsigned long long d;
    asm("fma.rn.f32x2 %0, %1, %2, %3;" : "=l"(d) : "l"(a), "l"(b), "l"(c));
    return d;
}
__device__ __forceinline__ unsigned long long dup2(float a) {
    unsigned long long r;
    asm("mov.b64 %0, {%1, %1};" : "=l"(r) : "f"(a));
    return r;
}
__device__ __forceinline__ unsigned long long packf(float lo, float hi) {
    unsigned long long r;
    asm("mov.b64 %0, {%1, %2};" : "=l"(r) : "f"(lo), "f"(hi));
    return r;
}
__device__ __forceinline__ float lof(unsigned long long v) {
    return __uint_as_float((unsigned)(v & 0xffffffffull));
}
__device__ __forceinline__ float hif(unsigned long long v) {
    return __uint_as_float((unsigned)(v >> 32));
}

__device__ __forceinline__ void red_v4(float* p, float a, float b, float c, float d) {
    asm volatile("red.global.add.v4.f32 [%0], {%1, %2, %3, %4};"
                 :: "l"(p), "f"(a), "f"(b), "f"(c), "f"(d) : "memory");
}

// ---------- GEMM 1: 4x8 tile, 64-row A tile (measured best for N=128) ----------
#define AS_STRIDE 129
#define G1_SMEM_BYTES ((64 * AS_STRIDE + 128 * 64) * 4)

__global__ __launch_bounds__(128) void gemm1_kernel(
    const float* __restrict__ A, const float* __restrict__ W,
    const float* __restrict__ bias, int M)
{
    extern __shared__ __align__(16) float smem[];
    float* A_sh = smem;                   // 64 * 129
    float* W_sh = smem + 64 * AS_STRIDE;  // 128 * 64
    float* C = g_h;
    const int N = 128;

    const int t = threadIdx.x;
    const int cg = t & 7;
    const int rg = t >> 3;
    const int m0 = blockIdx.x * 64;

    for (int lin = t; lin < 64 * 128; lin += 128) {
        int m = lin >> 7, k = lin & 127;
        A_sh[m * AS_STRIDE + k] = (m0 + m < M) ? A[(size_t)(m0 + m) * 128 + k] : 0.f;
    }
    __syncthreads();

    for (int n0 = 0; n0 < N; n0 += 64) {
        for (int idx = t; idx < 128 * 16; idx += 128) {
            int k = idx >> 4, j = idx & 15;
            ((float4*)(W_sh + k * 64))[j] = ((const float4*)(W + (size_t)k * N + n0))[j];
        }
        __syncthreads();

        unsigned long long acc[4][4];
        #pragma unroll
        for (int i = 0; i < 4; i++)
            #pragma unroll
            for (int j = 0; j < 4; j++) acc[i][j] = 0ull;

        const float* arow = A_sh + rg * 4 * AS_STRIDE;
        const float* wcol = W_sh + cg * 8;

        #pragma unroll 8
        for (int k = 0; k < 128; k++) {
            ulonglong2 wA = *(const ulonglong2*)(wcol + k * 64);
            ulonglong2 wB = *(const ulonglong2*)(wcol + k * 64 + 4);
            #pragma unroll
            for (int i = 0; i < 4; i++) {
                unsigned long long a2 = dup2(arow[i * AS_STRIDE + k]);
                acc[i][0] = fma2(a2, wA.x, acc[i][0]);
                acc[i][1] = fma2(a2, wA.y, acc[i][1]);
                acc[i][2] = fma2(a2, wB.x, acc[i][2]);
                acc[i][3] = fma2(a2, wB.y, acc[i][3]);
            }
        }

        const int ncol = n0 + cg * 8;
        #pragma unroll
        for (int i = 0; i < 4; i++) {
            const int m = m0 + rg * 4 + i;
            if (m < M) {
                float c[8];
                #pragma unroll
                for (int j = 0; j < 4; j++) {
                    c[2 * j]     = lof(acc[i][j]) + bias[ncol + 2 * j];
                    c[2 * j + 1] = hif(acc[i][j]) + bias[ncol + 2 * j + 1];
                }
                #pragma unroll
                for (int j = 0; j < 8; j++)
                    c[j] = c[j] / (1.0f + __expf(-c[j]));  // silu
                float4* outp = (float4*)(C + (size_t)m * N + ncol);
                outp[0] = make_float4(c[0], c[1], c[2], c[3]);
                outp[1] = make_float4(c[4], c[5], c[6], c[7]);
            }
        }
        __syncthreads();
    }
}

// ---------- GEMM 2: 8x8 tile, 128-row A tile (measured best for N=384) ----------
#define G2_SMEM_BYTES ((128 * AS_STRIDE + 128 * 64) * 4)

__global__ __launch_bounds__(128) void gemm2_kernel(
    const float* __restrict__ W, const float* __restrict__ bias, int M)
{
    extern __shared__ __align__(16) float smem[];
    float* A_sh = smem;                    // 128 * 129
    float* W_sh = smem + 128 * AS_STRIDE;  // 128 * 64
    const float* A = g_h;
    float* C = g_spass;
    const int N = 384;

    const int t = threadIdx.x;
    const int cg = t & 7;
    const int rg = t >> 3;
    const int m0 = blockIdx.x * 128;

    for (int lin = t; lin < 128 * 128; lin += 128) {
        int m = lin >> 7, k = lin & 127;
        A_sh[m * AS_STRIDE + k] = (m0 + m < M) ? A[(size_t)(m0 + m) * 128 + k] : 0.f;
    }
    __syncthreads();

    for (int n0 = 0; n0 < N; n0 += 64) {
        for (int idx = t; idx < 128 * 16; idx += 128) {
            int k = idx >> 4, j = idx & 15;
            ((float4*)(W_sh + k * 64))[j] = ((const float4*)(W + (size_t)k * N + n0))[j];
        }
        __syncthreads();

        unsigned long long acc[8][4];
        #pragma unroll
        for (int i = 0; i < 8; i++)
            #pragma unroll
            for (int j = 0; j < 4; j++) acc[i][j] = 0ull;

        const float* arow = A_sh + rg * 8 * AS_STRIDE;
        const float* wcol = W_sh + cg * 8;

        #pragma unroll 4
        for (int k = 0; k < 128; k++) {
            ulonglong2 wA = *(const ulonglong2*)(wcol + k * 64);
            ulonglong2 wB = *(const ulonglong2*)(wcol + k * 64 + 4);
            #pragma unroll
            for (int i = 0; i < 8; i++) {
                unsigned long long a2 = dup2(arow[i * AS_STRIDE + k]);
                acc[i][0] = fma2(a2, wA.x, acc[i][0]);
                acc[i][1] = fma2(a2, wA.y, acc[i][1]);
                acc[i][2] = fma2(a2, wB.x, acc[i][2]);
                acc[i][3] = fma2(a2, wB.y, acc[i][3]);
            }
        }

        const int ncol = n0 + cg * 8;
        #pragma unroll
        for (int i = 0; i < 8; i++) {
            const int m = m0 + rg * 8 + i;
            if (m < M) {
                float c[8];
                #pragma unroll
                for (int j = 0; j < 4; j++) {
                    c[2 * j]     = lof(acc[i][j]) + bias[ncol + 2 * j];
                    c[2 * j + 1] = hif(acc[i][j]) + bias[ncol + 2 * j + 1];
                }
                float4* outp = (float4*)(C + (size_t)m * N + ncol);
                outp[0] = make_float4(c[0], c[1], c[2], c[3]);
                outp[1] = make_float4(c[4], c[5], c[6], c[7]);
            }
        }
        __syncthreads();
    }
}

// ---------- Edge kernel v2: vectorized gathers + red.v4 scatters ----------
// 96 threads, 64 edges/block, waves of 8 edges.
// role j = t>>5 (0:dvg 1:ds 2:rep), q = t&31 -> 4 contiguous cols j*128+4q..+3.
#define EPB 64
#define WAVE 8

__global__ __launch_bounds__(96) void edge_kernel(
    const int* __restrict__ edges,         // [E][2] int32
    const float* __restrict__ r_ij,        // [E]
    const float* __restrict__ rnorm,       // [E][3]
    const float* __restrict__ Wr,          // [20][384]
    const float* __restrict__ br,          // [384]
    const float* __restrict__ v_in,        // [N][3][128]
    float* __restrict__ s_out,             // [N][128]
    float* __restrict__ v_out,             // [N][3][128]
    int n_edges)
{
    __shared__ __align__(16) float rbf_sh[EPB][20];   // 80B rows, 16B aligned
    __shared__ float fc_sh[EPB];
    __shared__ float rn_sh[EPB][3];
    __shared__ int src_sh[EPB];
    __shared__ int dst_sh[EPB];
    __shared__ __align__(16) float dvg_st[WAVE][128];
    __shared__ __align__(16) float rep_st[WAVE][128];

    const int t = threadIdx.x;
    const int j = t >> 5;        // role / warp
    const int q = t & 31;        // chunk
    const int col = j * 128 + 4 * q;
    const int base = blockIdx.x * EPB;

    // per-thread Wr columns as f32x2 pairs over n: wrP[c][p]
    unsigned long long wrP[4][10];
    float brc[4];
    #pragma unroll
    for (int c = 0; c < 4; c++) {
        brc[c] = br[col + c];
        #pragma unroll
        for (int p = 0; p < 10; p++)
            wrP[c][p] = packf(Wr[(2 * p) * 384 + col + c],
                              Wr[(2 * p + 1) * 384 + col + c]);
    }

    // init phase: threads 0..63 compute per-edge rbf / fc / geometry
    if (t < EPB) {
        const int e_g = base + t;
        if (e_g < n_edges) {
            int2 ed = ((const int2*)edges)[e_g];
            src_sh[t] = ed.x;
            dst_sh[t] = ed.y;
            float r = r_ij[e_g];
            float inv_r = 1.0f / r;
            float qq = r * 0.2f;
            #pragma unroll
            for (int n = 1; n <= NRBF; n++)
                rbf_sh[t][n - 1] = sinpif((float)n * qq) * inv_r;
            fc_sh[t] = (r <= 5.0f) ? 0.5f * (cospif(qq) + 1.0f) : 0.0f;
            rn_sh[t][0] = rnorm[3 * e_g + 0];
            rn_sh[t][1] = rnorm[3 * e_g + 1];
            rn_sh[t][2] = rnorm[3 * e_g + 2];
        }
    }
    __syncthreads();

    for (int wave = 0; wave < EPB / WAVE; wave++) {
        // ---- compute phase: pass_out block j, 4 cols, 8 edges
        #pragma unroll
        for (int w = 0; w < WAVE; w++) {
            const int e = wave * WAVE + w;
            if (base + e >= n_edges) continue;
            const int dst = dst_sh[e];

            ulonglong2 rp01 = ((const ulonglong2*)rbf_sh[e])[0];
            ulonglong2 rp23 = ((const ulonglong2*)rbf_sh[e])[1];
            ulonglong2 rp45 = ((const ulonglong2*)rbf_sh[e])[2];
            ulonglong2 rp67 = ((const ulonglong2*)rbf_sh[e])[3];
            ulonglong2 rp89 = ((const ulonglong2*)rbf_sh[e])[4];

            float4 sp4 = *(const float4*)(g_spass + (size_t)dst * 384 + col);
            const float fc = fc_sh[e];

            float out[4];
            #pragma unroll
            for (int c = 0; c < 4; c++) {
                unsigned long long a = 0ull;
                a = fma2(rp01.x, wrP[c][0], a);
                a = fma2(rp01.y, wrP[c][1], a);
                a = fma2(rp23.x, wrP[c][2], a);
                a = fma2(rp23.y, wrP[c][3], a);
                a = fma2(rp45.x, wrP[c][4], a);
                a = fma2(rp45.y, wrP[c][5], a);
                a = fma2(rp67.x, wrP[c][6], a);
                a = fma2(rp67.y, wrP[c][7], a);
                a = fma2(rp89.x, wrP[c][8], a);
                a = fma2(rp89.y, wrP[c][9], a);
                out[c] = (lof(a) + hif(a) + brc[c]) * fc;
            }
            out[0] *= sp4.x; out[1] *= sp4.y; out[2] *= sp4.z; out[3] *= sp4.w;

            if (j == 1) {
                // delta_s: scatter directly
                red_v4(s_out + (size_t)src_sh[e] * 128 + 4 * q,
                       out[0], out[1], out[2], out[3]);
            } else if (j == 0) {
                *(float4*)&dvg_st[w][4 * q] = make_float4(out[0], out[1], out[2], out[3]);
            } else {
                *(float4*)&rep_st[w][4 * q] = make_float4(out[0], out[1], out[2], out[3]);
            }
        }
        __syncthreads();

        // ---- v phase: thread (comp=j, chunk=q) per edge
        #pragma unroll
        for (int w = 0; w < WAVE; w++) {
            const int e = wave * WAVE + w;
            if (base + e >= n_edges) continue;
            const int src = src_sh[e];
            const int dst = dst_sh[e];
            const float rn = rn_sh[e][j];

            float4 dvg4 = *(const float4*)&dvg_st[w][4 * q];
            float4 rep4 = *(const float4*)&rep_st[w][4 * q];
            float4 v4 = *(const float4*)(v_in + (size_t)dst * 384 + j * 128 + 4 * q);

            red_v4(v_out + (size_t)src * 384 + j * 128 + 4 * q,
                   fmaf(v4.x, dvg4.x, rn * rep4.x),
                   fmaf(v4.y, dvg4.y, rn * rep4.y),
                   fmaf(v4.z, dvg4.z, rn * rep4.z),
                   fmaf(v4.w, dvg4.w, rn * rep4.w));
        }
        __syncthreads();
    }
}

// ---------- launch ----------
extern "C" void kernel_launch(void* const* d_in, const int* in_sizes, int n_in,
                              void* d_out, int out_size)
{
    const float* s     = (const float*)d_in[0];
    const float* v     = (const float*)d_in[1];
    const int*   edges = (const int*)d_in[2];
    const float* r_ij  = (const float*)d_in[3];
    const float* rnorm = (const float*)d_in[4];
    const float* W1    = (const float*)d_in[5];
    const float* b1    = (const float*)d_in[6];
    const float* W2    = (const float*)d_in[7];
    const float* b2    = (const float*)d_in[8];
    const float* Wr    = (const float*)d_in[9];
    const float* br    = (const float*)d_in[10];

    const int n_nodes = in_sizes[0] / EMB;
    const int n_edges = in_sizes[2] / 2;

    float* s_out = (float*)d_out;
    float* v_out = s_out + (size_t)n_nodes * EMB;

    // one-time host-side resource setup (no device memory involved)
    static cudaStream_t s2 = nullptr;
    static cudaEvent_t ev_fork = nullptr, ev_join = nullptr;
    if (!s2) {
        cudaStreamCreateWithFlags(&s2, cudaStreamNonBlocking);
        cudaEventCreateWithFlags(&ev_fork, cudaEventDisableTiming);
        cudaEventCreateWithFlags(&ev_join, cudaEventDisableTiming);
        cudaFuncSetAttribute(gemm1_kernel,
            cudaFuncAttributeMaxDynamicSharedMemorySize, G1_SMEM_BYTES);
        cudaFuncSetAttribute(gemm2_kernel,
            cudaFuncAttributeMaxDynamicSharedMemorySize, G2_SMEM_BYTES);
    }

    // fork: output-init copies on side stream, overlapped with GEMMs
    cudaEventRecord(ev_fork, 0);
    cudaStreamWaitEvent(s2, ev_fork, 0);
    cudaMemcpyAsync(s_out, s, (size_t)n_nodes * EMB * sizeof(float),
                    cudaMemcpyDeviceToDevice, s2);
    cudaMemcpyAsync(v_out, v, (size_t)n_nodes * 3 * EMB * sizeof(float),
                    cudaMemcpyDeviceToDevice, s2);
    cudaEventRecord(ev_join, s2);

    gemm1_kernel<<<(n_nodes + 63) / 64, 128, G1_SMEM_BYTES>>>(s, W1, b1, n_nodes);
    gemm2_kernel<<<(n_nodes + 127) / 128, 128, G2_SMEM_BYTES>>>(W2, b2, n_nodes);

    // join: edge kernel needs initialized outputs + g_spass
    cudaStreamWaitEvent(0, ev_join, 0);
    edge_kernel<<<(n_edges + EPB - 1) / EPB, 96>>>(edges, r_ij, rnorm, Wr, br,
                                                   v, s_out, v_out, n_edges);
}

// round 8
// speedup vs baseline: 2.1698x; 2.1698x over previous
#include <cuda_runtime.h>
#include <cstdint>

#define N_NODES 50000
#define MAX_EDGES 800000
#define EMB 128
#define NRBF 20

// Scratch (static device arrays are allowed; runtime alloc is not)
__device__ float g_h[(size_t)N_NODES * EMB];         // silu(s@W1+b1)
__device__ float g_spass[(size_t)N_NODES * 3 * EMB]; // h@W2+b2
__device__ int   g_hist[N_NODES];                    // histogram -> offsets (cursor)
__device__ int2  g_sorted_sd[MAX_EDGES];             // (src, dst) sorted by dst
__device__ int   g_sorted_idx[MAX_EDGES];            // original edge index

// ---------- f32x2 helpers ----------
__device__ __forceinline__ unsigned long long fma2(unsigned long long a,
                                                   unsigned long long b,
                                                   unsigned long long c) {
    unsigned long long d;
    asm("fma.rn.f32x2 %0, %1, %2, %3;" : "=l"(d) : "l"(a), "l"(b), "l"(c));
    return d;
}
__device__ __forceinline__ unsigned long long dup2(float a) {
    unsigned long long r;
    asm("mov.b64 %0, {%1, %1};" : "=l"(r) : "f"(a));
    return r;
}
__device__ __forceinline__ unsigned long long packf(float lo, float hi) {
    unsigned long long r;
    asm("mov.b64 %0, {%1, %2};" : "=l"(r) : "f"(lo), "f"(hi));
    return r;
}
__device__ __forceinline__ float lof(unsigned long long v) {
    return __uint_as_float((unsigned)(v & 0xffffffffull));
}
__device__ __forceinline__ float hif(unsigned long long v) {
    return __uint_as_float((unsigned)(v >> 32));
}

// ---------- GEMM 1: 4x8 tile, 64-row A tile (measured best for N=128) ----------
#define AS_STRIDE 129
#define G1_SMEM_BYTES ((64 * AS_STRIDE + 128 * 64) * 4)

__global__ __launch_bounds__(128) void gemm1_kernel(
    const float* __restrict__ A, const float* __restrict__ W,
    const float* __restrict__ bias, int M)
{
    extern __shared__ __align__(16) float smem[];
    float* A_sh = smem;                   // 64 * 129
    float* W_sh = smem + 64 * AS_STRIDE;  // 128 * 64
    float* C = g_h;
    const int N = 128;

    const int t = threadIdx.x;
    const int cg = t & 7;
    const int rg = t >> 3;
    const int m0 = blockIdx.x * 64;

    for (int lin = t; lin < 64 * 128; lin += 128) {
        int m = lin >> 7, k = lin & 127;
        A_sh[m * AS_STRIDE + k] = (m0 + m < M) ? A[(size_t)(m0 + m) * 128 + k] : 0.f;
    }
    __syncthreads();

    for (int n0 = 0; n0 < N; n0 += 64) {
        for (int idx = t; idx < 128 * 16; idx += 128) {
            int k = idx >> 4, j = idx & 15;
            ((float4*)(W_sh + k * 64))[j] = ((const float4*)(W + (size_t)k * N + n0))[j];
        }
        __syncthreads();

        unsigned long long acc[4][4];
        #pragma unroll
        for (int i = 0; i < 4; i++)
            #pragma unroll
            for (int j = 0; j < 4; j++) acc[i][j] = 0ull;

        const float* arow = A_sh + rg * 4 * AS_STRIDE;
        const float* wcol = W_sh + cg * 8;

        #pragma unroll 8
        for (int k = 0; k < 128; k++) {
            ulonglong2 wA = *(const ulonglong2*)(wcol + k * 64);
            ulonglong2 wB = *(const ulonglong2*)(wcol + k * 64 + 4);
            #pragma unroll
            for (int i = 0; i < 4; i++) {
                unsigned long long a2 = dup2(arow[i * AS_STRIDE + k]);
                acc[i][0] = fma2(a2, wA.x, acc[i][0]);
                acc[i][1] = fma2(a2, wA.y, acc[i][1]);
                acc[i][2] = fma2(a2, wB.x, acc[i][2]);
                acc[i][3] = fma2(a2, wB.y, acc[i][3]);
            }
        }

        const int ncol = n0 + cg * 8;
        #pragma unroll
        for (int i = 0; i < 4; i++) {
            const int m = m0 + rg * 4 + i;
            if (m < M) {
                float c[8];
                #pragma unroll
                for (int j = 0; j < 4; j++) {
                    c[2 * j]     = lof(acc[i][j]) + bias[ncol + 2 * j];
                    c[2 * j + 1] = hif(acc[i][j]) + bias[ncol + 2 * j + 1];
                }
                #pragma unroll
                for (int j = 0; j < 8; j++)
                    c[j] = c[j] / (1.0f + __expf(-c[j]));  // silu
                float4* outp = (float4*)(C + (size_t)m * N + ncol);
                outp[0] = make_float4(c[0], c[1], c[2], c[3]);
                outp[1] = make_float4(c[4], c[5], c[6], c[7]);
            }
        }
        __syncthreads();
    }
}

// ---------- GEMM 2: 8x8 tile, 128-row A tile (measured best for N=384) ----------
#define G2_SMEM_BYTES ((128 * AS_STRIDE + 128 * 64) * 4)

__global__ __launch_bounds__(128) void gemm2_kernel(
    const float* __restrict__ W, const float* __restrict__ bias, int M)
{
    extern __shared__ __align__(16) float smem[];
    float* A_sh = smem;                    // 128 * 129
    float* W_sh = smem + 128 * AS_STRIDE;  // 128 * 64
    const float* A = g_h;
    float* C = g_spass;
    const int N = 384;

    const int t = threadIdx.x;
    const int cg = t & 7;
    const int rg = t >> 3;
    const int m0 = blockIdx.x * 128;

    for (int lin = t; lin < 128 * 128; lin += 128) {
        int m = lin >> 7, k = lin & 127;
        A_sh[m * AS_STRIDE + k] = (m0 + m < M) ? A[(size_t)(m0 + m) * 128 + k] : 0.f;
    }
    __syncthreads();

    for (int n0 = 0; n0 < N; n0 += 64) {
        for (int idx = t; idx < 128 * 16; idx += 128) {
            int k = idx >> 4, j = idx & 15;
            ((float4*)(W_sh + k * 64))[j] = ((const float4*)(W + (size_t)k * N + n0))[j];
        }
        __syncthreads();

        unsigned long long acc[8][4];
        #pragma unroll
        for (int i = 0; i < 8; i++)
            #pragma unroll
            for (int j = 0; j < 4; j++) acc[i][j] = 0ull;

        const float* arow = A_sh + rg * 8 * AS_STRIDE;
        const float* wcol = W_sh + cg * 8;

        #pragma unroll 4
        for (int k = 0; k < 128; k++) {
            ulonglong2 wA = *(const ulonglong2*)(wcol + k * 64);
            ulonglong2 wB = *(const ulonglong2*)(wcol + k * 64 + 4);
            #pragma unroll
            for (int i = 0; i < 8; i++) {
                unsigned long long a2 = dup2(arow[i * AS_STRIDE + k]);
                acc[i][0] = fma2(a2, wA.x, acc[i][0]);
                acc[i][1] = fma2(a2, wA.y, acc[i][1]);
                acc[i][2] = fma2(a2, wB.x, acc[i][2]);
                acc[i][3] = fma2(a2, wB.y, acc[i][3]);
            }
        }

        const int ncol = n0 + cg * 8;
        #pragma unroll
        for (int i = 0; i < 8; i++) {
            const int m = m0 + rg * 8 + i;
            if (m < M) {
                float c[8];
                #pragma unroll
                for (int j = 0; j < 4; j++) {
                    c[2 * j]     = lof(acc[i][j]) + bias[ncol + 2 * j];
                    c[2 * j + 1] = hif(acc[i][j]) + bias[ncol + 2 * j + 1];
                }
                float4* outp = (float4*)(C + (size_t)m * N + ncol);
                outp[0] = make_float4(c[0], c[1], c[2], c[3]);
                outp[1] = make_float4(c[4], c[5], c[6], c[7]);
            }
        }
        __syncthreads();
    }
}

// ---------- counting sort of edges by dst ----------
__global__ __launch_bounds__(256) void hist_kernel(const int* __restrict__ edges,
                                                   int n_edges)
{
    int e = blockIdx.x * 256 + threadIdx.x;
    if (e < n_edges) {
        int dst = edges[2 * e + 1];
        atomicAdd(&g_hist[dst], 1);
    }
}

// single-block exclusive prefix sum over g_hist (in place)
__global__ __launch_bounds__(1024) void scan_kernel()
{
    __shared__ int warp_sums[32];
    __shared__ int running_sh;
    const int t = threadIdx.x;
    const int lane = t & 31, wid = t >> 5;
    if (t == 0) running_sh = 0;
    __syncthreads();

    for (int base = 0; base < N_NODES; base += 1024) {
        int i = base + t;
        int v = (i < N_NODES) ? g_hist[i] : 0;
        // inclusive scan within warp
        int x = v;
        #pragma unroll
        for (int d = 1; d < 32; d <<= 1) {
            int y = __shfl_up_sync(~0u, x, d);
            if (lane >= d) x += y;
        }
        if (lane == 31) warp_sums[wid] = x;
        __syncthreads();
        if (wid == 0) {
            int s2 = warp_sums[lane];
            #pragma unroll
            for (int d = 1; d < 32; d <<= 1) {
                int y = __shfl_up_sync(~0u, s2, d);
                if (lane >= d) s2 += y;
            }
            warp_sums[lane] = s2;
        }
        __syncthreads();
        int incl = x + (wid > 0 ? warp_sums[wid - 1] : 0) + running_sh;
        if (i < N_NODES) g_hist[i] = incl - v;  // exclusive
        __syncthreads();
        if (t == 1023) running_sh = incl;
        __syncthreads();
    }
}

__global__ __launch_bounds__(256) void scatter_kernel(const int* __restrict__ edges,
                                                      int n_edges)
{
    int e = blockIdx.x * 256 + threadIdx.x;
    if (e < n_edges) {
        int2 sd = ((const int2*)edges)[e];
        int pos = atomicAdd(&g_hist[sd.y], 1);
        g_sorted_sd[pos] = sd;
        g_sorted_idx[pos] = e;
    }
}

// ---------- Edge kernel: dst-sorted, register-cached gathers ----------
// block: 128 threads, chunk of 128 sorted edges.
// thread t owns output columns t (delta_v_g), t+128 (delta_s), t+256 (delta_rep).
__global__ __launch_bounds__(128) void edge_kernel(
    const float* __restrict__ r_ij,        // [E]
    const float* __restrict__ rnorm,       // [E][3]
    const float* __restrict__ Wr,          // [20][384]
    const float* __restrict__ br,          // [384]
    const float* __restrict__ v_in,        // [N][3][128]
    float* __restrict__ s_out,             // [N][128]
    float* __restrict__ v_out,             // [N][3][128]
    int n_edges)
{
    __shared__ __align__(16) float rb_sh[128][24];  // 20 rbf, fc, rn0..rn2
    __shared__ int src_sh[128];
    __shared__ int dst_sh[128];

    const int t = threadIdx.x;
    const int base = blockIdx.x * 128;

    // Preload Wr columns (packed pairs over n) + bias
    unsigned long long wrP0[10], wrP1[10], wrP2[10];
    #pragma unroll
    for (int p = 0; p < 10; p++) {
        wrP0[p] = packf(Wr[(2 * p) * 384 + t],       Wr[(2 * p + 1) * 384 + t]);
        wrP1[p] = packf(Wr[(2 * p) * 384 + 128 + t], Wr[(2 * p + 1) * 384 + 128 + t]);
        wrP2[p] = packf(Wr[(2 * p) * 384 + 256 + t], Wr[(2 * p + 1) * 384 + 256 + t]);
    }
    const float br0 = br[t], br1 = br[128 + t], br2 = br[256 + t];

    // Phase 1: thread t computes sorted-edge (base+t)'s rbf / fcut / geometry
    const int e_my = base + t;
    if (e_my < n_edges) {
        int2 sd = g_sorted_sd[e_my];
        int idx = g_sorted_idx[e_my];
        src_sh[t] = sd.x;
        dst_sh[t] = sd.y;
        float r = r_ij[idx];
        float inv_r = 1.0f / r;
        float q = r * 0.2f;  // r / R_CUT
        #pragma unroll
        for (int n = 1; n <= NRBF; n++) {
            rb_sh[t][n - 1] = sinpif((float)n * q) * inv_r;
        }
        float fc = (r <= 5.0f) ? 0.5f * (cospif(q) + 1.0f) : 0.0f;
        rb_sh[t][20] = fc;
        rb_sh[t][21] = rnorm[3 * idx + 0];
        rb_sh[t][22] = rnorm[3 * idx + 1];
        rb_sh[t][23] = rnorm[3 * idx + 2];
    }
    __syncthreads();

    const int cnt = min(128, n_edges - base);

    int dst_prev = -1;
    float sp0 = 0.f, sp1 = 0.f, sp2 = 0.f, vv0 = 0.f, vv1 = 0.f, vv2 = 0.f;

    for (int e = 0; e < cnt; e++) {
        const int src = src_sh[e];
        const int dst = dst_sh[e];

        // dst-sorted: reload gathers only on dst change (uniform across block)
        if (dst != dst_prev) {
            const float* sp = g_spass + (size_t)dst * 384 + t;
            const float* vp = v_in + (size_t)dst * 384 + t;
            sp0 = sp[0]; sp1 = sp[128]; sp2 = sp[256];
            vv0 = vp[0]; vv1 = vp[128]; vv2 = vp[256];
            dst_prev = dst;
        }

        const float* row = rb_sh[e];
        unsigned long long a0 = 0ull, a1 = 0ull, a2 = 0ull;
        #pragma unroll
        for (int p = 0; p < 5; p++) {
            ulonglong2 rp = ((const ulonglong2*)row)[p];
            a0 = fma2(rp.x, wrP0[2 * p], a0);
            a0 = fma2(rp.y, wrP0[2 * p + 1], a0);
            a1 = fma2(rp.x, wrP1[2 * p], a1);
            a1 = fma2(rp.y, wrP1[2 * p + 1], a1);
            a2 = fma2(rp.x, wrP2[2 * p], a2);
            a2 = fma2(rp.y, wrP2[2 * p + 1], a2);
        }
        const float fc  = row[20];
        const float rn0 = row[21], rn1 = row[22], rn2 = row[23];

        float g   = (lof(a0) + hif(a0) + br0) * fc * sp0;
        float ds  = (lof(a1) + hif(a1) + br1) * fc * sp1;
        float rep = (lof(a2) + hif(a2) + br2) * fc * sp2;

        atomicAdd(s_out + (size_t)src * 128 + t, ds);

        float* vo = v_out + (size_t)src * 384 + t;
        atomicAdd(vo,       fmaf(vv0, g, rn0 * rep));
        atomicAdd(vo + 128, fmaf(vv1, g, rn1 * rep));
        atomicAdd(vo + 256, fmaf(vv2, g, rn2 * rep));
    }
}

// ---------- launch ----------
extern "C" void kernel_launch(void* const* d_in, const int* in_sizes, int n_in,
                              void* d_out, int out_size)
{
    const float* s     = (const float*)d_in[0];
    const float* v     = (const float*)d_in[1];
    const int*   edges = (const int*)d_in[2];
    const float* r_ij  = (const float*)d_in[3];
    const float* rnorm = (const float*)d_in[4];
    const float* W1    = (const float*)d_in[5];
    const float* b1    = (const float*)d_in[6];
    const float* W2    = (const float*)d_in[7];
    const float* b2    = (const float*)d_in[8];
    const float* Wr    = (const float*)d_in[9];
    const float* br    = (const float*)d_in[10];

    const int n_nodes = in_sizes[0] / EMB;
    const int n_edges = in_sizes[2] / 2;

    float* s_out = (float*)d_out;
    float* v_out = s_out + (size_t)n_nodes * EMB;

    // one-time host-side resource setup (no device memory involved)
    static cudaStream_t s2 = nullptr;
    static cudaEvent_t ev_fork = nullptr, ev_join = nullptr;
    static int* hist_ptr = nullptr;
    if (!s2) {
        cudaStreamCreateWithFlags(&s2, cudaStreamNonBlocking);
        cudaEventCreateWithFlags(&ev_fork, cudaEventDisableTiming);
        cudaEventCreateWithFlags(&ev_join, cudaEventDisableTiming);
        cudaFuncSetAttribute(gemm1_kernel,
            cudaFuncAttributeMaxDynamicSharedMemorySize, G1_SMEM_BYTES);
        cudaFuncSetAttribute(gemm2_kernel,
            cudaFuncAttributeMaxDynamicSharedMemorySize, G2_SMEM_BYTES);
        cudaGetSymbolAddress((void**)&hist_ptr, g_hist);
    }

    // fork: side stream does output-init copies + edge sort, overlapped with GEMMs
    cudaEventRecord(ev_fork, 0);
    cudaStreamWaitEvent(s2, ev_fork, 0);
    cudaMemcpyAsync(s_out, s, (size_t)n_nodes * EMB * sizeof(float),
                    cudaMemcpyDeviceToDevice, s2);
    cudaMemcpyAsync(v_out, v, (size_t)n_nodes * 3 * EMB * sizeof(float),
                    cudaMemcpyDeviceToDevice, s2);
    cudaMemsetAsync(hist_ptr, 0, N_NODES * sizeof(int), s2);
    hist_kernel<<<(n_edges + 255) / 256, 256, 0, s2>>>(edges, n_edges);
    scan_kernel<<<1, 1024, 0, s2>>>();
    scatter_kernel<<<(n_edges + 255) / 256, 256, 0, s2>>>(edges, n_edges);
    cudaEventRecord(ev_join, s2);

    gemm1_kernel<<<(n_nodes + 63) / 64, 128, G1_SMEM_BYTES>>>(s, W1, b1, n_nodes);
    gemm2_kernel<<<(n_nodes + 127) / 128, 128, G2_SMEM_BYTES>>>(W2, b2, n_nodes);

    // join: edge kernel needs sorted edges + initialized outputs + g_spass
    cudaStreamWaitEvent(0, ev_join, 0);
    edge_kernel<<<(n_edges + 127) / 128, 128>>>(r_ij, rnorm, Wr, br,
                                                v, s_out, v_out, n_edges);
}

// round 9
// speedup vs baseline: 2.5661x; 1.1826x over previous
#include <cuda_runtime.h>
#include <cstdint>

#define N_NODES 50000
#define MAX_EDGES 800000
#define EMB 128
#define NRBF 20

// Scratch (static device arrays are allowed; runtime alloc is not)
__device__ float g_h[(size_t)N_NODES * EMB];         // silu(s@W1+b1)
__device__ float g_spass[(size_t)N_NODES * 3 * EMB]; // h@W2+b2
__device__ int   g_hist[N_NODES];                    // histogram -> offsets (cursor)
__device__ int2  g_sorted_sd[MAX_EDGES];             // (src, dst) sorted by dst
__device__ int   g_sorted_idx[MAX_EDGES];            // original edge index

// ---------- f32x2 helpers (edge kernel) ----------
__device__ __forceinline__ unsigned long long fma2(unsigned long long a,
                                                   unsigned long long b,
                                                   unsigned long long c) {
    unsigned long long d;
    asm("fma.rn.f32x2 %0, %1, %2, %3;" : "=l"(d) : "l"(a), "l"(b), "l"(c));
    return d;
}
__device__ __forceinline__ unsigned long long packf(float lo, float hi) {
    unsigned long long r;
    asm("mov.b64 %0, {%1, %2};" : "=l"(r) : "f"(lo), "f"(hi));
    return r;
}
__device__ __forceinline__ float lof(unsigned long long v) {
    return __uint_as_float((unsigned)(v & 0xffffffffull));
}
__device__ __forceinline__ float hif(unsigned long long v) {
    return __uint_as_float((unsigned)(v >> 32));
}

// ---------- tf32 mma helpers ----------
__device__ __forceinline__ unsigned tf32_of(float f) {
    unsigned r;
    asm("cvt.rna.tf32.f32 %0, %1;" : "=r"(r) : "f"(f));
    return r;
}
__device__ __forceinline__ void mma_tf32(float c[4],
                                         unsigned a0, unsigned a1,
                                         unsigned a2, unsigned a3,
                                         unsigned b0, unsigned b1) {
    asm("mma.sync.aligned.m16n8k8.row.col.f32.tf32.tf32.f32 "
        "{%0,%1,%2,%3}, {%4,%5,%6,%7}, {%8,%9}, {%0,%1,%2,%3};"
        : "+f"(c[0]), "+f"(c[1]), "+f"(c[2]), "+f"(c[3])
        : "r"(a0), "r"(a1), "r"(a2), "r"(a3), "r"(b0), "r"(b1));
}

// ---------- tensor-core GEMM: C[M x N] = act(A[M x 128] @ W[128 x N] + b) ----------
// 256 threads / 8 warps. Block tile 128(M) x 64(N) per n-pass; warp tile 32x32
// (warps 4m x 2n). A (tf32) staged fully [128][128]; W in 32-row k-chunks.
// A_STRIDE=132 (bank 4*lr+lc distinct), W_STRIDE=72 (bank 8*lc+lr distinct).
#define A_STRIDE 132
#define W_STRIDE 72
#define TG_SMEM_BYTES ((128 * A_STRIDE + 32 * W_STRIDE) * 4)

template <int N, int ACT>
__device__ __forceinline__ void gemm_tc_body(
    const float* __restrict__ A, const float* __restrict__ W,
    const float* __restrict__ bias, float* __restrict__ C, int M)
{
    extern __shared__ __align__(16) unsigned smem_u[];
    unsigned* A_sh = smem_u;                    // [128][A_STRIDE]
    unsigned* W_sh = smem_u + 128 * A_STRIDE;   // [32][W_STRIDE]

    const int t = threadIdx.x;
    const int w = t >> 5;
    const int lane = t & 31;
    const int mw = w & 3;        // 0..3 (m warp)
    const int nw = w >> 2;       // 0..1 (n warp)
    const int lr = lane >> 2;    // 0..7
    const int lc = lane & 3;     // 0..3
    const int m0 = blockIdx.x * 128;

    // stage A tile (128 x 128) with tf32 rounding
    for (int lin = t; lin < 128 * 128; lin += 256) {
        int m = lin >> 7, k = lin & 127;
        float val = (m0 + m < M) ? A[(size_t)(m0 + m) * 128 + k] : 0.f;
        A_sh[m * A_STRIDE + k] = tf32_of(val);
    }
    // consumers first read after the __syncthreads at top of the kc loop

    for (int n0 = 0; n0 < N; n0 += 64) {
        float acc[2][4][4];
        #pragma unroll
        for (int i = 0; i < 2; i++)
            #pragma unroll
            for (int j = 0; j < 4; j++)
                #pragma unroll
                for (int x = 0; x < 4; x++) acc[i][j][x] = 0.f;

        #pragma unroll 1
        for (int kc = 0; kc < 4; kc++) {
            __syncthreads();  // protect W_sh (and order A_sh staging on first pass)
            for (int lin = t; lin < 32 * 64; lin += 256) {
                int kk = lin >> 6, nn = lin & 63;
                W_sh[kk * W_STRIDE + nn] =
                    tf32_of(W[(size_t)(kc * 32 + kk) * N + n0 + nn]);
            }
            __syncthreads();

            #pragma unroll
            for (int k8 = 0; k8 < 4; k8++) {
                const int kl = k8 * 8;          // k within chunk
                const int kg = kc * 32 + kl;    // absolute k (A)
                unsigned a[2][4];
                #pragma unroll
                for (int i = 0; i < 2; i++) {
                    const int r = mw * 32 + i * 16 + lr;
                    a[i][0] = A_sh[r * A_STRIDE + kg + lc];
                    a[i][1] = A_sh[(r + 8) * A_STRIDE + kg + lc];
                    a[i][2] = A_sh[r * A_STRIDE + kg + lc + 4];
                    a[i][3] = A_sh[(r + 8) * A_STRIDE + kg + lc + 4];
                }
                #pragma unroll
                for (int j = 0; j < 4; j++) {
                    const int n = nw * 32 + j * 8 + lr;
                    unsigned b0 = W_sh[(kl + lc) * W_STRIDE + n];
                    unsigned b1 = W_sh[(kl + lc + 4) * W_STRIDE + n];
                    mma_tf32(acc[0][j], a[0][0], a[0][1], a[0][2], a[0][3], b0, b1);
                    mma_tf32(acc[1][j], a[1][0], a[1][1], a[1][2], a[1][3], b0, b1);
                }
            }
        }

        // epilogue: bias (+silu), STG.64 pairs
        #pragma unroll
        for (int i = 0; i < 2; i++) {
            const int r1 = m0 + mw * 32 + i * 16 + lr;
            const int r2 = r1 + 8;
            #pragma unroll
            for (int j = 0; j < 4; j++) {
                const int cb = n0 + nw * 32 + j * 8 + lc * 2;
                const float b0f = bias[cb], b1f = bias[cb + 1];
                float x0 = acc[i][j][0] + b0f;
                float x1 = acc[i][j][1] + b1f;
                float x2 = acc[i][j][2] + b0f;
                float x3 = acc[i][j][3] + b1f;
                if (ACT) {
                    x0 = x0 / (1.0f + __expf(-x0));
                    x1 = x1 / (1.0f + __expf(-x1));
                    x2 = x2 / (1.0f + __expf(-x2));
                    x3 = x3 / (1.0f + __expf(-x3));
                }
                if (r1 < M) *(float2*)(C + (size_t)r1 * N + cb) = make_float2(x0, x1);
                if (r2 < M) *(float2*)(C + (size_t)r2 * N + cb) = make_float2(x2, x3);
            }
        }
    }
}

__global__ __launch_bounds__(256) void gemm1_kernel(
    const float* __restrict__ A, const float* __restrict__ W,
    const float* __restrict__ bias, int M)
{
    gemm_tc_body<128, 1>(A, W, bias, g_h, M);
}

__global__ __launch_bounds__(256) void gemm2_kernel(
    const float* __restrict__ W, const float* __restrict__ bias, int M)
{
    gemm_tc_body<384, 0>(g_h, W, bias, g_spass, M);
}

// ---------- counting sort of edges by dst ----------
__global__ __launch_bounds__(256) void hist_kernel(const int* __restrict__ edges,
                                                   int n_edges)
{
    int e = blockIdx.x * 256 + threadIdx.x;
    if (e < n_edges) {
        int dst = edges[2 * e + 1];
        atomicAdd(&g_hist[dst], 1);
    }
}

// single-block exclusive prefix sum over g_hist (in place)
__global__ __launch_bounds__(1024) void scan_kernel()
{
    __shared__ int warp_sums[32];
    __shared__ int running_sh;
    const int t = threadIdx.x;
    const int lane = t & 31, wid = t >> 5;
    if (t == 0) running_sh = 0;
    __syncthreads();

    for (int base = 0; base < N_NODES; base += 1024) {
        int i = base + t;
        int v = (i < N_NODES) ? g_hist[i] : 0;
        int x = v;
        #pragma unroll
        for (int d = 1; d < 32; d <<= 1) {
            int y = __shfl_up_sync(~0u, x, d);
            if (lane >= d) x += y;
        }
        if (lane == 31) warp_sums[wid] = x;
        __syncthreads();
        if (wid == 0) {
            int s2 = warp_sums[lane];
            #pragma unroll
            for (int d = 1; d < 32; d <<= 1) {
                int y = __shfl_up_sync(~0u, s2, d);
                if (lane >= d) s2 += y;
            }
            warp_sums[lane] = s2;
        }
        __syncthreads();
        int incl = x + (wid > 0 ? warp_sums[wid - 1] : 0) + running_sh;
        if (i < N_NODES) g_hist[i] = incl - v;  // exclusive
        __syncthreads();
        if (t == 1023) running_sh = incl;
        __syncthreads();
    }
}

__global__ __launch_bounds__(256) void scatter_kernel(const int* __restrict__ edges,
                                                      int n_edges)
{
    int e = blockIdx.x * 256 + threadIdx.x;
    if (e < n_edges) {
        int2 sd = ((const int2*)edges)[e];
        int pos = atomicAdd(&g_hist[sd.y], 1);
        g_sorted_sd[pos] = sd;
        g_sorted_idx[pos] = e;
    }
}

// ---------- Edge kernel: dst-sorted, register-cached gathers ----------
__global__ __launch_bounds__(128) void edge_kernel(
    const float* __restrict__ r_ij,        // [E]
    const float* __restrict__ rnorm,       // [E][3]
    const float* __restrict__ Wr,          // [20][384]
    const float* __restrict__ br,          // [384]
    const float* __restrict__ v_in,        // [N][3][128]
    float* __restrict__ s_out,             // [N][128]
    float* __restrict__ v_out,             // [N][3][128]
    int n_edges)
{
    __shared__ __align__(16) float rb_sh[128][24];  // 20 rbf, fc, rn0..rn2
    __shared__ int src_sh[128];
    __shared__ int dst_sh[128];

    const int t = threadIdx.x;
    const int base = blockIdx.x * 128;

    unsigned long long wrP0[10], wrP1[10], wrP2[10];
    #pragma unroll
    for (int p = 0; p < 10; p++) {
        wrP0[p] = packf(Wr[(2 * p) * 384 + t],       Wr[(2 * p + 1) * 384 + t]);
        wrP1[p] = packf(Wr[(2 * p) * 384 + 128 + t], Wr[(2 * p + 1) * 384 + 128 + t]);
        wrP2[p] = packf(Wr[(2 * p) * 384 + 256 + t], Wr[(2 * p + 1) * 384 + 256 + t]);
    }
    const float br0 = br[t], br1 = br[128 + t], br2 = br[256 + t];

    const int e_my = base + t;
    if (e_my < n_edges) {
        int2 sd = g_sorted_sd[e_my];
        int idx = g_sorted_idx[e_my];
        src_sh[t] = sd.x;
        dst_sh[t] = sd.y;
        float r = r_ij[idx];
        float inv_r = 1.0f / r;
        float q = r * 0.2f;
        #pragma unroll
        for (int n = 1; n <= NRBF; n++) {
            rb_sh[t][n - 1] = sinpif((float)n * q) * inv_r;
        }
        float fc = (r <= 5.0f) ? 0.5f * (cospif(q) + 1.0f) : 0.0f;
        rb_sh[t][20] = fc;
        rb_sh[t][21] = rnorm[3 * idx + 0];
        rb_sh[t][22] = rnorm[3 * idx + 1];
        rb_sh[t][23] = rnorm[3 * idx + 2];
    }
    __syncthreads();

    const int cnt = min(128, n_edges - base);

    int dst_prev = -1;
    float sp0 = 0.f, sp1 = 0.f, sp2 = 0.f, vv0 = 0.f, vv1 = 0.f, vv2 = 0.f;

    for (int e = 0; e < cnt; e++) {
        const int src = src_sh[e];
        const int dst = dst_sh[e];

        if (dst != dst_prev) {
            const float* sp = g_spass + (size_t)dst * 384 + t;
            const float* vp = v_in + (size_t)dst * 384 + t;
            sp0 = sp[0]; sp1 = sp[128]; sp2 = sp[256];
            vv0 = vp[0]; vv1 = vp[128]; vv2 = vp[256];
            dst_prev = dst;
        }

        const float* row = rb_sh[e];
        unsigned long long a0 = 0ull, a1 = 0ull, a2 = 0ull;
        #pragma unroll
        for (int p = 0; p < 5; p++) {
            ulonglong2 rp = ((const ulonglong2*)row)[p];
            a0 = fma2(rp.x, wrP0[2 * p], a0);
            a0 = fma2(rp.y, wrP0[2 * p + 1], a0);
            a1 = fma2(rp.x, wrP1[2 * p], a1);
            a1 = fma2(rp.y, wrP1[2 * p + 1], a1);
            a2 = fma2(rp.x, wrP2[2 * p], a2);
            a2 = fma2(rp.y, wrP2[2 * p + 1], a2);
        }
        const float fc  = row[20];
        const float rn0 = row[21], rn1 = row[22], rn2 = row[23];

        float g   = (lof(a0) + hif(a0) + br0) * fc * sp0;
        float ds  = (lof(a1) + hif(a1) + br1) * fc * sp1;
        float rep = (lof(a2) + hif(a2) + br2) * fc * sp2;

        atomicAdd(s_out + (size_t)src * 128 + t, ds);

        float* vo = v_out + (size_t)src * 384 + t;
        atomicAdd(vo,       fmaf(vv0, g, rn0 * rep));
        atomicAdd(vo + 128, fmaf(vv1, g, rn1 * rep));
        atomicAdd(vo + 256, fmaf(vv2, g, rn2 * rep));
    }
}

// ---------- launch ----------
extern "C" void kernel_launch(void* const* d_in, const int* in_sizes, int n_in,
                              void* d_out, int out_size)
{
    const float* s     = (const float*)d_in[0];
    const float* v     = (const float*)d_in[1];
    const int*   edges = (const int*)d_in[2];
    const float* r_ij  = (const float*)d_in[3];
    const float* rnorm = (const float*)d_in[4];
    const float* W1    = (const float*)d_in[5];
    const float* b1    = (const float*)d_in[6];
    const float* W2    = (const float*)d_in[7];
    const float* b2    = (const float*)d_in[8];
    const float* Wr    = (const float*)d_in[9];
    const float* br    = (const float*)d_in[10];

    const int n_nodes = in_sizes[0] / EMB;
    const int n_edges = in_sizes[2] / 2;

    float* s_out = (float*)d_out;
    float* v_out = s_out + (size_t)n_nodes * EMB;

    static cudaStream_t s2 = nullptr;
    static cudaEvent_t ev_fork = nullptr, ev_join = nullptr;
    static int* hist_ptr = nullptr;
    if (!s2) {
        cudaStreamCreateWithFlags(&s2, cudaStreamNonBlocking);
        cudaEventCreateWithFlags(&ev_fork, cudaEventDisableTiming);
        cudaEventCreateWithFlags(&ev_join, cudaEventDisableTiming);
        cudaFuncSetAttribute(gemm1_kernel,
            cudaFuncAttributeMaxDynamicSharedMemorySize, TG_SMEM_BYTES);
        cudaFuncSetAttribute(gemm2_kernel,
            cudaFuncAttributeMaxDynamicSharedMemorySize, TG_SMEM_BYTES);
        cudaGetSymbolAddress((void**)&hist_ptr, g_hist);
    }

    // fork: side stream does output-init copies + edge sort, overlapped with GEMMs
    cudaEventRecord(ev_fork, 0);
    cudaStreamWaitEvent(s2, ev_fork, 0);
    cudaMemcpyAsync(s_out, s, (size_t)n_nodes * EMB * sizeof(float),
                    cudaMemcpyDeviceToDevice, s2);
    cudaMemcpyAsync(v_out, v, (size_t)n_nodes * 3 * EMB * sizeof(float),
                    cudaMemcpyDeviceToDevice, s2);
    cudaMemsetAsync(hist_ptr, 0, N_NODES * sizeof(int), s2);
    hist_kernel<<<(n_edges + 255) / 256, 256, 0, s2>>>(edges, n_edges);
    scan_kernel<<<1, 1024, 0, s2>>>();
    scatter_kernel<<<(n_edges + 255) / 256, 256, 0, s2>>>(edges, n_edges);
    cudaEventRecord(ev_join, s2);

    const int tc_grid = (n_nodes + 127) / 128;
    gemm1_kernel<<<tc_grid, 256, TG_SMEM_BYTES>>>(s, W1, b1, n_nodes);
    gemm2_kernel<<<tc_grid, 256, TG_SMEM_BYTES>>>(W2, b2, n_nodes);

    // join: edge kernel needs sorted edges + initialized outputs + g_spass
    cudaStreamWaitEvent(0, ev_join, 0);
    edge_kernel<<<(n_edges + 127) / 128, 128>>>(r_ij, rnorm, Wr, br,
                                                v, s_out, v_out, n_edges);
}